// round 14
// baseline (speedup 1.0000x reference)
#include <cuda_runtime.h>
#include <math.h>

#define NUM_NODES   8192
#define MEME_DIM    64
#define VISION      2048
#define K_IN        32
#define VOCAB_N     256
#define G_TOT       (NUM_NODES * MEME_DIM)
#define TILE_FLOATS 16384
#define TILE_BYTES  65536
#define GRID_P      148
#define RTHREADS    512
#define NBUF        3

// Scratch (device globals; no allocation allowed)
__device__ float  d_g_raw[G_TOT];
__device__ float2 d_partials[NUM_NODES];

__device__ __forceinline__ float fast_tanh(float x) {
    float r;
    asm("tanh.approx.f32 %0, %1;" : "=f"(r) : "f"(x));
    return r;
}
__device__ __forceinline__ unsigned smem_u32(const void* p) {
    unsigned r;
    asm("{ .reg .u64 t; cvta.to.shared.u64 t, %1; cvt.u32.u64 %0, t; }"
        : "=r"(r) : "l"(p));
    return r;
}
__device__ __forceinline__ void mbar_init(unsigned a, unsigned c) {
    asm volatile("mbarrier.init.shared.b64 [%0], %1;" :: "r"(a), "r"(c) : "memory");
}
__device__ __forceinline__ void mbar_expect_tx(unsigned a, unsigned b) {
    asm volatile("mbarrier.arrive.expect_tx.shared.b64 _, [%0], %1;"
                 :: "r"(a), "r"(b) : "memory");
}
__device__ __forceinline__ void bulk_ldgsts(unsigned dst, const void* src,
                                            unsigned bytes, unsigned mbar) {
    asm volatile(
        "cp.async.bulk.shared::cta.global.mbarrier::complete_tx::bytes "
        "[%0], [%1], %2, [%3];"
        :: "r"(dst), "l"(src), "r"(bytes), "r"(mbar) : "memory");
}
__device__ __forceinline__ void mbar_wait(unsigned a, unsigned ph) {
    asm volatile(
        "{\n\t.reg .pred P;\n\t"
        "W_%=:\n\t"
        "mbarrier.try_wait.parity.acquire.cta.shared::cta.b64 P, [%0], %1, 0x989680;\n\t"
        "@!P bra W_%=;\n\t}"
        :: "r"(a), "r"(ph) : "memory");
}

// ---------------------------------------------------------------------------
// Kernel 1: gather + mean (warp per node, high occupancy) — unchanged (7.9us)
// ---------------------------------------------------------------------------
__global__ __launch_bounds__(256) void gather_kernel(
    const float* __restrict__ x,
    const float* __restrict__ memes,
    const int*   __restrict__ idx)
{
    const int wid  = threadIdx.x >> 5;
    const int lane = threadIdx.x & 31;
    const int n    = blockIdx.x * 8 + wid;
    const int f4   = lane & 15;
    const int kh   = lane >> 4;

    const int myidx = __ldg(idx + (size_t)n * K_IN + lane);

    const float4* x4 = (const float4*)x;
    const float4* m4 = (const float4*)memes;

    float4 acc = make_float4(0.f, 0.f, 0.f, 0.f);
#pragma unroll
    for (int j = 0; j < 16; j++) {
        const int r = __shfl_sync(0xffffffffu, myidx, kh + 2 * j);
        const float4* src = (r < VISION) ? (x4 + (size_t)r * 16)
                                         : (m4 + (size_t)(r - VISION) * 16);
        const float4 v = __ldg(src + f4);
        acc.x += v.x; acc.y += v.y; acc.z += v.z; acc.w += v.w;
    }
    acc.x += __shfl_xor_sync(0xffffffffu, acc.x, 16);
    acc.y += __shfl_xor_sync(0xffffffffu, acc.y, 16);
    acc.z += __shfl_xor_sync(0xffffffffu, acc.z, 16);
    acc.w += __shfl_xor_sync(0xffffffffu, acc.w, 16);

    float4 g;
    g.x = acc.x * (1.f / 32.f); g.y = acc.y * (1.f / 32.f);
    g.z = acc.z * (1.f / 32.f); g.w = acc.w * (1.f / 32.f);

    if (kh == 0)
        ((float4*)(d_g_raw + (size_t)n * MEME_DIM))[f4] = g;

    float s = g.x + g.y + g.z + g.w;
    float q = g.x * g.x + g.y * g.y + g.z * g.z + g.w * g.w;
#pragma unroll
    for (int o = 8; o > 0; o >>= 1) {
        s += __shfl_down_sync(0xffffffffu, s, o, 16);
        q += __shfl_down_sync(0xffffffffu, q, o, 16);
    }
    if (lane == 0) d_partials[n] = make_float2(s, q);
}

// ---------------------------------------------------------------------------
// Kernel 2: remix with fused global stats. TMA 3-deep smem ring feeds a
// single register tile; compute identical to R11. 2 barriers/tile.
// ---------------------------------------------------------------------------
__global__ __launch_bounds__(RTHREADS, 1) void remix_kernel(
    const float* __restrict__ vocab,
    const float* __restrict__ raw_sc,
    const float* __restrict__ raw_sh,
    float*       __restrict__ out)
{
    extern __shared__ __align__(128) float dsm[];
    float*  bufs = dsm;                                   // 3 * 16384 floats
    float4* pd4  = (float4*)(dsm + NBUF * TILE_FLOATS);   // 2048 floats (8KB)
    float*  po   = dsm + NBUF * TILE_FLOATS + 2048;       // 4096 floats (16KB)
    float*  fs   = po + 4096;                             // 256 floats
    __shared__ __align__(8) unsigned long long mbar_s[NBUF];
    __shared__ float ws[4], wq[4], wp[4];

    const int tid  = threadIdx.x;
    const int lane = tid & 31, w = tid >> 5;
    const int c4   = tid & 63;
    const int ch   = tid >> 6;
    const int n0   = blockIdx.x;

    unsigned mb[NBUF], sb[NBUF];
#pragma unroll
    for (int i = 0; i < NBUF; i++) {
        mb[i] = smem_u32(&mbar_s[i]);
        sb[i] = smem_u32(bufs + i * TILE_FLOATS);
    }

    if (tid == 0) {
#pragma unroll
        for (int i = 0; i < NBUF; i++) mbar_init(mb[i], 1);
        asm volatile("fence.proxy.async.shared::cta;" ::: "memory");
    }
    __syncthreads();

    // issue first NBUF tile fills (stream during the stats phase below)
    if (tid == 0) {
#pragma unroll
        for (int i = 0; i < NBUF; i++) {
            const int nn = n0 + i * GRID_P;
            if (nn < NUM_NODES) {
                mbar_expect_tx(mb[i], TILE_BYTES);
                bulk_ldgsts(sb[i], vocab + (size_t)nn * TILE_FLOATS, TILE_BYTES, mb[i]);
            }
        }
    }

    // ---- fused global stats (redundant per CTA, deterministic) ----
    float mean, istd;
    {
        double* dsum = (double*)po;                       // 1024 doubles fit 16KB
        double* dsq  = dsum + RTHREADS;
        double s = 0.0, q = 0.0;
        for (int i = tid; i < NUM_NODES; i += RTHREADS) {
            float2 p = d_partials[i];
            s += (double)p.x;
            q += (double)p.y;
        }
        dsum[tid] = s; dsq[tid] = q;
        __syncthreads();
        for (int st = RTHREADS / 2; st > 0; st >>= 1) {
            if (tid < st) { dsum[tid] += dsum[tid + st]; dsq[tid] += dsq[tid + st]; }
            __syncthreads();
        }
        const double N = (double)G_TOT;
        const double mn  = dsum[0] / N;
        const double var = (dsq[0] - dsum[0] * dsum[0] / N) / (N - 1.0);
        mean = (float)mn;
        istd = (float)(1.0 / sqrt(var));
        __syncthreads();                                   // release po
    }

    const float sc     = __expf(__ldg(raw_sc));
    const float inv_sc = __fdividef(1.f, sc);
    const float lnsh   = __ldg(raw_sh);

    auto reduce_prev = [&](int n_prev) {
        const int t  = tid - 128;
        const int eo = t >> 2;
        const int p4 = t & 3;
        const float4* pr = (const float4*)(po + eo * 64 + p4 * 16);
        const float4 r0 = pr[0], r1 = pr[1], r2 = pr[2], r3 = pr[3];
        float s = r0.x + r0.y + r0.z + r0.w + r1.x + r1.y + r1.z + r1.w
                + r2.x + r2.y + r2.z + r2.w + r3.x + r3.y + r3.z + r3.w;
        s += __shfl_down_sync(0xffffffffu, s, 2, 4);
        s += __shfl_down_sync(0xffffffffu, s, 1, 4);
        if (p4 == 0) out[(size_t)n_prev * MEME_DIM + eo] = s;
    };

    // g row for first tile
    float4 ga, gb;
    {
        const float4* g4 = (const float4*)(d_g_raw + (size_t)n0 * MEME_DIM);
        ga = __ldg(g4 + ch * 2);
        gb = __ldg(g4 + ch * 2 + 1);
    }

    int slot = 0, phase = 0;
    int n_last = n0;
    for (int n = n0; n < NUM_NODES; n += GRID_P) {
        // ---- wait tile, stage smem -> registers (conflict-free LDS.128) ----
        mbar_wait(mb[slot], phase);
        float4 cur[8];
        {
            const float4* vb = (const float4*)(bufs + slot * TILE_FLOATS);
#pragma unroll
            for (int j = 0; j < 8; j++)
                cur[j] = vb[(ch * 8 + j) * 64 + c4];
        }

        // prefetch next tile's g row (LDG in flight across the step)
        float4 gna, gnb;
        const int nn = n + GRID_P;
        if (nn < NUM_NODES) {
            const float4* g4n = (const float4*)(d_g_raw + (size_t)nn * MEME_DIM);
            gna = __ldg(g4n + ch * 2);
            gnb = __ldg(g4n + ch * 2 + 1);
        }

        // standardize g
        float gr[8];
        gr[0] = (ga.x - mean) * istd; gr[1] = (ga.y - mean) * istd;
        gr[2] = (ga.z - mean) * istd; gr[3] = (ga.w - mean) * istd;
        gr[4] = (gb.x - mean) * istd; gr[5] = (gb.y - mean) * istd;
        gr[6] = (gb.z - mean) * istd; gr[7] = (gb.w - mean) * istd;

        // ---- phase B: dot partials ----
        {
            float4 a = make_float4(0.f, 0.f, 0.f, 0.f);
#pragma unroll
            for (int j = 0; j < 8; j++) {
                a.x = fmaf(gr[j], cur[j].x, a.x);
                a.y = fmaf(gr[j], cur[j].y, a.y);
                a.z = fmaf(gr[j], cur[j].z, a.z);
                a.w = fmaf(gr[j], cur[j].w, a.w);
            }
            pd4[ch * 64 + c4] = a;
        }
        __syncthreads();                                   // barrier 1 (buffer free)

        // refill this slot with tile n + 3*GRID_P (prefetch distance 3)
        if (tid == 0) {
            const int nf = n + NBUF * GRID_P;
            if (nf < NUM_NODES) {
                asm volatile("fence.proxy.async.shared::cta;" ::: "memory");
                mbar_expect_tx(mb[slot], TILE_BYTES);
                bulk_ldgsts(sb[slot], vocab + (size_t)nf * TILE_FLOATS, TILE_BYTES, mb[slot]);
            }
        }

        if (tid < 128) {
            // ---- stats + fractions: lane t owns cols 2t, 2t+1 ----
            const float2* pd2 = (const float2*)pd4;
            float d0 = 0.f, d1 = 0.f;
#pragma unroll
            for (int k = 0; k < 8; k++) {
                float2 p = pd2[k * 128 + tid];
                d0 += p.x; d1 += p.y;
            }
            float s = d0 + d1;
            float q = d0 * d0 + d1 * d1;
#pragma unroll
            for (int o = 16; o > 0; o >>= 1) {
                s += __shfl_down_sync(0xffffffffu, s, o);
                q += __shfl_down_sync(0xffffffffu, q, o);
            }
            if (lane == 0) { ws[w] = s; wq[w] = q; }
            asm volatile("bar.sync 8, 128;" ::: "memory");
            const float bsum = ws[0] + ws[1] + ws[2] + ws[3];
            const float bsq  = wq[0] + wq[1] + wq[2] + wq[3];

            const float m = bsum * (1.f / 256.f);
            float var = (bsq - bsum * bsum * (1.f / 256.f)) * (1.f / 255.f);
            var = fmaxf(var, 0.f);
            const float inv_sd = __fdividef(1.f, sqrtf(var) + 0.001f);

            float p0 = __expf(fast_tanh((d0 - m) * inv_sd * inv_sc) * sc * lnsh);
            float p1 = __expf(fast_tanh((d1 - m) * inv_sd * inv_sc) * sc * lnsh);

            float ps = p0 + p1;
#pragma unroll
            for (int o = 16; o > 0; o >>= 1)
                ps += __shfl_down_sync(0xffffffffu, ps, o);
            if (lane == 0) wp[w] = ps;
            asm volatile("bar.sync 8, 128;" ::: "memory");
            const float psum = wp[0] + wp[1] + wp[2] + wp[3];
            const float inv_psum = __fdividef(1.f, psum + 0.001f);

            ((float2*)fs)[tid] = make_float2(p0 * inv_psum, p1 * inv_psum);
        } else if (tid < 384 && n != n0) {
            reduce_prev(n - GRID_P);                       // output of previous tile
        }
        __syncthreads();                                   // barrier 2

        // ---- phase E: out partials from register tile ----
        {
            const float4 f = ((const float4*)fs)[c4];
#pragma unroll
            for (int j = 0; j < 8; j++) {
                float p = cur[j].x * f.x + cur[j].y * f.y
                        + cur[j].z * f.z + cur[j].w * f.w;
                po[(ch * 8 + j) * 64 + c4] = p;
            }
        }
        // no barrier: next iteration's barrier 1 orders po reads

        ga = gna; gb = gnb;
        n_last = n;
        if (++slot == NBUF) { slot = 0; phase ^= 1; }
    }

    __syncthreads();
    if (tid >= 128 && tid < 384) reduce_prev(n_last);
}

// ---------------------------------------------------------------------------
extern "C" void kernel_launch(void* const* d_in, const int* in_sizes, int n_in,
                              void* d_out, int out_size)
{
    const float* x      = (const float*)d_in[0];
    const float* memes  = (const float*)d_in[1];
    const int*   idx    = (const int*)  d_in[2];
    const float* vocab  = (const float*)d_in[3];
    const float* raw_sc = (const float*)d_in[4];
    const float* raw_sh = (const float*)d_in[5];
    float* out = (float*)d_out;

    const int smem_bytes = (NBUF * TILE_FLOATS + 2048 + 4096 + 256) * sizeof(float); // 222208
    static int attr_set = 0;
    if (!attr_set) {
        cudaFuncSetAttribute(remix_kernel, cudaFuncAttributeMaxDynamicSharedMemorySize, smem_bytes);
        attr_set = 1;
    }

    gather_kernel<<<NUM_NODES / 8, 256>>>(x, memes, idx);
    remix_kernel<<<GRID_P, RTHREADS, smem_bytes>>>(vocab, raw_sc, raw_sh, out);
}